// round 10
// baseline (speedup 1.0000x reference)
#include <cuda_runtime.h>
#include <cuda_bf16.h>
#include <cstdint>

// ---------------------------------------------------------------------------
// SegFormerXAttention: B=4, Lv=1024, Lt=256, H=16, DH=64, D=1024
//
//   0) detect_mask_mode : on-device dtype of the bool masks
//   1) convert_all      : fp32 -> (bf16 hi, bf16 lo) split of A and W slabs
//   2) proj_mma x2      : HMMA bf16 3-term-split GEMM (128x64 CTA tile,
//                         2 CTAs/SM, 80B-pitch conflict-free LDSM, frag
//                         prefetch); epilogue writes Q/K/V hi/lo attn layout
//   3) attn_fused       : flash-attention (QK^T + mask + online softmax + PV)
// ---------------------------------------------------------------------------

namespace cfg {
constexpr int D  = 1024;
constexpr int H  = 16;
constexpr int DH = 64;
constexpr int B  = 4;
constexpr int LV = 1024;
constexpr int LT = 256;
constexpr int LK = LV + LT;   // 1280
constexpr int DD = D * D;
}

// ---- input splits ----------------------------------------------------------
__device__ __nv_bfloat16 g_AVhi[(size_t)cfg::B * cfg::LV * cfg::D];
__device__ __nv_bfloat16 g_AVlo[(size_t)cfg::B * cfg::LV * cfg::D];
__device__ __nv_bfloat16 g_AThi[(size_t)cfg::B * cfg::LT * cfg::D];
__device__ __nv_bfloat16 g_ATlo[(size_t)cfg::B * cfg::LT * cfg::D];
__device__ __nv_bfloat16 g_WVhi[(size_t)6 * cfg::DD];
__device__ __nv_bfloat16 g_WVlo[(size_t)6 * cfg::DD];
__device__ __nv_bfloat16 g_WThi[(size_t)6 * cfg::DD];
__device__ __nv_bfloat16 g_WTlo[(size_t)6 * cfg::DD];

// ---- projection outputs, attention layout, bf16 hi/lo ----------------------
// Q: [b][slot(0/1)][h][tok][64]; K/V: [b][h][key 0..1279][64]
__device__ __nv_bfloat16 g_Qv_hi[(size_t)cfg::B * 2 * cfg::H * cfg::LV * 64];
__device__ __nv_bfloat16 g_Qv_lo[(size_t)cfg::B * 2 * cfg::H * cfg::LV * 64];
__device__ __nv_bfloat16 g_Qt_hi[(size_t)cfg::B * 2 * cfg::H * cfg::LT * 64];
__device__ __nv_bfloat16 g_Qt_lo[(size_t)cfg::B * 2 * cfg::H * cfg::LT * 64];
__device__ __nv_bfloat16 g_Kv_hi[(size_t)cfg::B * cfg::H * cfg::LK * 64];
__device__ __nv_bfloat16 g_Kv_lo[(size_t)cfg::B * cfg::H * cfg::LK * 64];
__device__ __nv_bfloat16 g_Kt_hi[(size_t)cfg::B * cfg::H * cfg::LK * 64];
__device__ __nv_bfloat16 g_Kt_lo[(size_t)cfg::B * cfg::H * cfg::LK * 64];
__device__ __nv_bfloat16 g_Vv_hi[(size_t)cfg::B * cfg::H * cfg::LK * 64];
__device__ __nv_bfloat16 g_Vv_lo[(size_t)cfg::B * cfg::H * cfg::LK * 64];
__device__ __nv_bfloat16 g_Vt_hi[(size_t)cfg::B * cfg::H * cfg::LK * 64];
__device__ __nv_bfloat16 g_Vt_lo[(size_t)cfg::B * cfg::H * cfg::LK * 64];

// 0 = float32 (1.0f/0.0f), 1 = int32 (1/0), 2 = packed uint8 bool
__device__ int g_maskMode;

__global__ void detect_mask_mode(const unsigned int* m) {
    if (threadIdx.x != 0) return;
    bool isF = false, isB = false;
    for (int i = 0; i < 64; i++) {
        unsigned int w = m[i];
        if (w == 0x3F800000u) isF = true;
        if (w == 0x01010101u) isB = true;
    }
    g_maskMode = isF ? 0 : (isB ? 2 : 1);
}

__device__ __forceinline__ bool mask_at(const void* m, int i) {
    const int mode = g_maskMode;
    if (mode == 0) return ((const float*)m)[i] != 0.0f;
    if (mode == 1) return ((const int*)m)[i] != 0;
    return ((const unsigned char*)m)[i] != 0;
}

// ---------------------------------------------------------------------------
// helpers
// ---------------------------------------------------------------------------
__device__ __forceinline__ uint32_t smem_u32(const void* p) {
    uint32_t a;
    asm("{ .reg .u64 t; cvta.to.shared.u64 t, %1; cvt.u32.u64 %0, t; }" : "=r"(a) : "l"(p));
    return a;
}
__device__ __forceinline__ void mma16816(float* d, const uint32_t* a, const uint32_t* b) {
    asm volatile(
        "mma.sync.aligned.m16n8k16.row.col.f32.bf16.bf16.f32 "
        "{%0,%1,%2,%3}, {%4,%5,%6,%7}, {%8,%9}, {%0,%1,%2,%3};"
        : "+f"(d[0]), "+f"(d[1]), "+f"(d[2]), "+f"(d[3])
        : "r"(a[0]), "r"(a[1]), "r"(a[2]), "r"(a[3]), "r"(b[0]), "r"(b[1]));
}
__device__ __forceinline__ void ldsm_x4(uint32_t* r, uint32_t addr) {
    asm volatile("ldmatrix.sync.aligned.m8n8.x4.shared.b16 {%0,%1,%2,%3}, [%4];"
                 : "=r"(r[0]), "=r"(r[1]), "=r"(r[2]), "=r"(r[3]) : "r"(addr));
}
__device__ __forceinline__ void ldsm_x4_t(uint32_t* r, uint32_t addr) {
    asm volatile("ldmatrix.sync.aligned.m8n8.x4.trans.shared.b16 {%0,%1,%2,%3}, [%4];"
                 : "=r"(r[0]), "=r"(r[1]), "=r"(r[2]), "=r"(r[3]) : "r"(addr));
}
__device__ __forceinline__ void cp16(uint32_t dst, const void* src) {
    asm volatile("cp.async.cg.shared.global [%0], [%1], 16;" :: "r"(dst), "l"(src));
}
#define CP_COMMIT() asm volatile("cp.async.commit_group;" ::: "memory")
#define CP_WAIT(N)  asm volatile("cp.async.wait_group %0;" :: "n"(N) : "memory")

// fp32 pair -> packed bf16 hi pair + bf16 lo pair
__device__ __forceinline__ void split2(float x, float y, uint32_t& hi, uint32_t& lo) {
    __nv_bfloat16 hx = __float2bfloat16(x), hy = __float2bfloat16(y);
    __nv_bfloat16 lx = __float2bfloat16(x - __bfloat162float(hx));
    __nv_bfloat16 ly = __float2bfloat16(y - __bfloat162float(hy));
    __nv_bfloat162 h2(hx, hy), l2(lx, ly);
    hi = *reinterpret_cast<uint32_t*>(&h2);
    lo = *reinterpret_cast<uint32_t*>(&l2);
}

// ---------------------------------------------------------------------------
// fp32 -> bf16 hi/lo split, all 14 slabs in one launch (grid-stride).
// dst: 0=AV 1=AT 2=WV(+slot) 3=WT(+slot)
// ---------------------------------------------------------------------------
struct CvtArgs { const float* src[14]; int dst[14]; int slot[14]; int n4[14]; };

__global__ __launch_bounds__(256) void convert_all(CvtArgs a) {
    const int job = blockIdx.y;
    const int slot = a.slot[job];
    const int n4 = a.n4[job];
    __nv_bfloat16 *hi, *lo;
    switch (a.dst[job]) {
        case 0:  hi = g_AVhi;                          lo = g_AVlo;                          break;
        case 1:  hi = g_AThi;                          lo = g_ATlo;                          break;
        case 2:  hi = g_WVhi + (size_t)slot * cfg::DD; lo = g_WVlo + (size_t)slot * cfg::DD; break;
        default: hi = g_WThi + (size_t)slot * cfg::DD; lo = g_WTlo + (size_t)slot * cfg::DD; break;
    }
    const float* src = a.src[job];
    for (int i = blockIdx.x * 256 + threadIdx.x; i < n4; i += gridDim.x * 256) {
        float4 v = ((const float4*)src)[i];
        uint32_t h01, l01, h23, l23;
        split2(v.x, v.y, h01, l01);
        split2(v.z, v.w, h23, l23);
        uint32_t* hp = (uint32_t*)(hi + (size_t)i * 4);
        uint32_t* lp = (uint32_t*)(lo + (size_t)i * 4);
        hp[0] = h01; hp[1] = h23;
        lp[0] = l01; lp[1] = l23;
    }
}

// ---------------------------------------------------------------------------
// HMMA projection GEMM v2.
// CTA tile 128(M) x 64(N), K=1024 in 32 chunks of 32, 3-term bf16 split.
// 8 warps: wr = w&3 row-group (32 rows), wc = w>>2 col-group (32 cols).
// SMEM stage (30720 B): Ahi[128x32]@0, Alo@10240, Bhi[64x32]@20480, Blo@25600,
// all with 80-byte row pitch (conflict-free ldmatrix, no swizzle).
// 2 stages; 2 CTAs/SM via __launch_bounds__(256,2).
// slot sel: 0,1 = Q (key-seg vid/txt); 2,3 = K (v/t stream); 4,5 = V.
// ---------------------------------------------------------------------------
struct TCBias { const float* p[6]; };

namespace pj {
constexpr int PITCH  = 80;
constexpr int ALO    = 10240;
constexpr int BHI    = 20480;
constexpr int BLO    = 25600;
constexpr int STAGE  = 30720;
constexpr int NCHUNK = 32;
}

__global__ __launch_bounds__(256, 2) void proj_mma(int isVid, TCBias bias) {
    using namespace cfg;
    using namespace pj;
    extern __shared__ char sm[];
    uint32_t sbase = smem_u32(sm);
    uint32_t padb  = (1024u - (sbase & 1023u)) & 1023u;
    const uint32_t sa = sbase + padb;

    const int tid = threadIdx.x;
    const int w = tid >> 5;
    const int L = tid & 31;
    const int wr = w & 3;          // 32-row group
    const int wc = w >> 2;         // 32-col group

    const int m0  = blockIdx.y * 128;
    const int nt  = blockIdx.x;    // 0..95
    const int sel = nt >> 4;
    const int c0  = (nt & 15) * 64;

    const __nv_bfloat16* Ah = (isVid ? g_AVhi : g_AThi) + (size_t)m0 * D;
    const __nv_bfloat16* Al = (isVid ? g_AVlo : g_ATlo) + (size_t)m0 * D;
    const __nv_bfloat16* Bh = (isVid ? g_WVhi : g_WThi) + (size_t)sel * DD + (size_t)c0 * D;
    const __nv_bfloat16* Bl = (isVid ? g_WVlo : g_WTlo) + (size_t)sel * DD + (size_t)c0 * D;

    // copy mapping
    const int ra = tid >> 1;              // A row 0..127
    const int ca = (tid & 1) * 32;        // byte col {0,32}
    const int rb = tid >> 2;              // B row 0..63
    const int cb = (tid & 3) * 16;        // byte col {0,16,32,48}
    const uint32_t adst = (uint32_t)(ra * PITCH + ca);
    const uint32_t bdst = (uint32_t)(rb * PITCH + cb);
    const __nv_bfloat16* asrcH = Ah + (size_t)ra * D + ca / 2;
    const __nv_bfloat16* asrcL = Al + (size_t)ra * D + ca / 2;
    const __nv_bfloat16* bsrcH = Bh + (size_t)rb * D + cb / 2;
    const __nv_bfloat16* bsrcL = Bl + (size_t)rb * D + cb / 2;

    // ldmatrix lane addressing
    const int aRow = wr * 32 + (L & 15);                   // + mi*16
    const int aCol = (L >> 4) * 16;                        // + kb
    const int bRow = wc * 32 + (L & 7) + ((L >> 4) << 3);  // + at*16
    const int bCol = ((L >> 3) & 1) * 16;                  // + kb

    float acc[2][4][4];
#pragma unroll
    for (int mi = 0; mi < 2; mi++)
#pragma unroll
        for (int ni = 0; ni < 4; ni++)
#pragma unroll
            for (int j = 0; j < 4; j++) acc[mi][ni][j] = 0.0f;

    // prefetch chunk 0
    {
        cp16(sa + adst,              asrcH);
        cp16(sa + adst + 16,         asrcH + 8);
        cp16(sa + ALO + adst,        asrcL);
        cp16(sa + ALO + adst + 16,   asrcL + 8);
        cp16(sa + BHI + bdst,        bsrcH);
        cp16(sa + BLO + bdst,        bsrcL);
        CP_COMMIT();
    }

    for (int c = 0; c < NCHUNK; ++c) {
        __syncthreads();
        if (c + 1 < NCHUNK) {
            const int k0 = (c + 1) * 32;
            const uint32_t sb = sa + ((c + 1) & 1) * STAGE;
            cp16(sb + adst,            asrcH + k0);
            cp16(sb + adst + 16,       asrcH + k0 + 8);
            cp16(sb + ALO + adst,      asrcL + k0);
            cp16(sb + ALO + adst + 16, asrcL + k0 + 8);
            cp16(sb + BHI + bdst,      bsrcH + k0);
            cp16(sb + BLO + bdst,      bsrcL + k0);
            CP_COMMIT();
            CP_WAIT(1);
        } else {
            CP_WAIT(0);
        }
        __syncthreads();

        const uint32_t sb = sa + (c & 1) * STAGE;

        uint32_t ah[2][2][4], al[2][2][4], bh[2][2][4], bl[2][2][4];
        // load set 0 (k16 = 0)
#pragma unroll
        for (int mi = 0; mi < 2; ++mi) {
            const uint32_t off = (uint32_t)((aRow + mi * 16) * PITCH + aCol);
            ldsm_x4(ah[0][mi], sb + off);
            ldsm_x4(al[0][mi], sb + ALO + off);
        }
#pragma unroll
        for (int at = 0; at < 2; ++at) {
            const uint32_t off = (uint32_t)((bRow + at * 16) * PITCH + bCol);
            ldsm_x4(bh[0][at], sb + BHI + off);
            ldsm_x4(bl[0][at], sb + BLO + off);
        }

#pragma unroll
        for (int k16 = 0; k16 < 2; ++k16) {
            if (k16 == 0) {
                // prefetch set 1 (k16 = 1, byte offset +32)
#pragma unroll
                for (int mi = 0; mi < 2; ++mi) {
                    const uint32_t off = (uint32_t)((aRow + mi * 16) * PITCH + aCol + 32);
                    ldsm_x4(ah[1][mi], sb + off);
                    ldsm_x4(al[1][mi], sb + ALO + off);
                }
#pragma unroll
                for (int at = 0; at < 2; ++at) {
                    const uint32_t off = (uint32_t)((bRow + at * 16) * PITCH + bCol + 32);
                    ldsm_x4(bh[1][at], sb + BHI + off);
                    ldsm_x4(bl[1][at], sb + BLO + off);
                }
            }
#pragma unroll
            for (int mi = 0; mi < 2; ++mi) {
#pragma unroll
                for (int ni = 0; ni < 4; ++ni) {
                    const uint32_t* b2h = &bh[k16][ni >> 1][(ni & 1) * 2];
                    const uint32_t* b2l = &bl[k16][ni >> 1][(ni & 1) * 2];
                    mma16816(acc[mi][ni], ah[k16][mi], b2h);
                    mma16816(acc[mi][ni], ah[k16][mi], b2l);
                    mma16816(acc[mi][ni], al[k16][mi], b2h);
                }
            }
        }
    }

    // ---- epilogue: bias + hi/lo split -> attention buffers ----------------
    const int lq  = L >> 2;
    const int tc2 = (L & 3) * 2;
    const float* bp = bias.p[sel];
    const int Lqd = isVid ? LV : LT;

    __nv_bfloat16 *dstHi, *dstLo;
    switch (sel) {
        case 0: case 1: dstHi = isVid ? g_Qv_hi : g_Qt_hi;
                        dstLo = isVid ? g_Qv_lo : g_Qt_lo; break;
        case 2: dstHi = g_Kv_hi; dstLo = g_Kv_lo; break;
        case 3: dstHi = g_Kt_hi; dstLo = g_Kt_lo; break;
        case 4: dstHi = g_Vv_hi; dstLo = g_Vv_lo; break;
        default: dstHi = g_Vt_hi; dstLo = g_Vt_lo; break;
    }

#pragma unroll
    for (int ni = 0; ni < 4; ++ni) {
        const int col_local = c0 + wc * 32 + ni * 8 + tc2;   // 0..1023 within slot
        const int hh = col_local >> 6;
        const int dh = col_local & 63;
        const float b0v = __ldg(bp + col_local);
        const float b1v = __ldg(bp + col_local + 1);
#pragma unroll
        for (int mi = 0; mi < 2; ++mi) {
            const int rbase = m0 + wr * 32 + mi * 16 + lq;
#pragma unroll
            for (int hf = 0; hf < 2; ++hf) {
                const int row = rbase + hf * 8;
                const int bb  = isVid ? (row >> 10) : (row >> 8);
                const int tok = isVid ? (row & 1023) : (row & 255);
                const float vx = acc[mi][ni][hf * 2]     + b0v;
                const float vy = acc[mi][ni][hf * 2 + 1] + b1v;
                uint32_t h2, l2;
                split2(vx, vy, h2, l2);
                size_t idx2;
                if (sel < 2)
                    idx2 = ((((size_t)bb * 2 + sel) * H + hh) * Lqd + tok) * 64 + dh;
                else {
                    const int key = isVid ? tok : (LV + tok);
                    idx2 = (((size_t)bb * H + hh) * LK + key) * 64 + dh;
                }
                *(uint32_t*)(dstHi + idx2) = h2;
                *(uint32_t*)(dstLo + idx2) = l2;
            }
        }
    }
}

// ---------------------------------------------------------------------------
// Fused flash attention (unchanged from R9).
// Grid: 640 CTAs. Per CTA: 128 q rows x 1280 keys in 10 k-tiles of 128.
// ---------------------------------------------------------------------------
namespace asm_off {
constexpr uint32_t KV0   = 65536;
constexpr uint32_t STAGE = 65536;
constexpr uint32_t FLAGS = 196608;
}

__global__ __launch_bounds__(256, 1) void attn_fused(
    const void* vmask, const void* tmask, float* out)
{
    using namespace cfg;
    extern __shared__ char sm[];
    uint32_t sbase = smem_u32(sm);
    uint32_t padb  = (1024u - (sbase & 1023u)) & 1023u;
    const uint32_t sa = sbase + padb;
    char* smp = sm + padb;

    const int tid = threadIdx.x;
    const int w = tid >> 5;
    const int L = tid & 31;

    int idx = blockIdx.x;
    int isV, bh, qt;
    if (idx < 512) { isV = 1; bh = idx >> 3; qt = idx & 7; }
    else { idx -= 512; isV = 0; bh = idx >> 1; qt = idx & 1; }
    const int b = bh >> 4, h = bh & 15;
    const int Lq = isV ? LV : LT;
    const int q0 = qt * 128;

    const __nv_bfloat16 *Qhi, *Qlo, *Khi, *Klo, *Vhi, *Vlo;
    float* obase;
    if (isV) { Qhi = g_Qv_hi; Qlo = g_Qv_lo; Khi = g_Kv_hi; Klo = g_Kv_lo;
               Vhi = g_Vv_hi; Vlo = g_Vv_lo; obase = out; }
    else     { Qhi = g_Qt_hi; Qlo = g_Qt_lo; Khi = g_Kt_hi; Klo = g_Kt_lo;
               Vhi = g_Vt_hi; Vlo = g_Vt_lo; obase = out + (size_t)B * LV * D; }

    float* qff = (float*)(smp + asm_off::FLAGS);
    float* kff = qff + 128;

    const int r     = tid >> 1;
    const int halfk = (tid & 1) * 32;
    const uint32_t swr = (uint32_t)((r & 7) << 4);

    {
#pragma unroll
        for (int s = 0; s < 2; s++) {
            const size_t src = ((((size_t)b * 2 + s) * H + h) * Lq + q0 + r) * 64 + halfk;
            const uint32_t dstb = sa + s * 32768;
#pragma unroll
            for (int i = 0; i < 4; i++) {
                uint32_t bo = (uint32_t)(r * 128 + (halfk + i * 8) * 2) ^ swr;
                cp16(dstb + bo,         Qhi + src + i * 8);
                cp16(dstb + 16384 + bo, Qlo + src + i * 8);
            }
        }
        const size_t src = (((size_t)b * H + h) * LK + r) * 64 + halfk;
        const uint32_t kv0 = sa + asm_off::KV0;
#pragma unroll
        for (int i = 0; i < 4; i++) {
            uint32_t bo = (uint32_t)(r * 128 + (halfk + i * 8) * 2) ^ swr;
            cp16(kv0 + bo,         Khi + src + i * 8);
            cp16(kv0 + 16384 + bo, Klo + src + i * 8);
            cp16(kv0 + 32768 + bo, Vhi + src + i * 8);
            cp16(kv0 + 49152 + bo, Vlo + src + i * 8);
        }
        CP_COMMIT();
    }

    const void* qmask = isV ? vmask : tmask;
    for (int i = tid; i < 128; i += 256)
        qff[i] = mask_at(qmask, b * Lq + q0 + i) ? 1.0f : 0.0f;
    for (int i = tid; i < LK; i += 256) {
        bool mk = (i < LV) ? mask_at(vmask, b * LV + i)
                           : mask_at(tmask, b * LT + i - LV);
        kff[i] = mk ? 1.0f : 0.0f;
    }
    __syncthreads();

    const int lq  = L >> 2;
    const int lc2 = (L & 3) * 2;
    const int a_r  = L & 15;
    const int a_cb = (L >> 4) * 16;
    const int b_r  = (L & 7) + ((L >> 4) << 3);
    const int b_cb = ((L >> 3) & 1) * 16;

    const float qf0 = qff[w * 16 + lq];
    const float qf1 = qff[w * 16 + lq + 8];

    float oacc[8][4];
#pragma unroll
    for (int a = 0; a < 8; a++)
#pragma unroll
        for (int j = 0; j < 4; j++) oacc[a][j] = 0.0f;
    float m0 = -1e30f, m1 = -1e30f, l0 = 0.0f, l1 = 0.0f;

    for (int kt = 0; kt < 10; ++kt) {
        __syncthreads();
        if (kt + 1 < 10) {
            const uint32_t sb = sa + asm_off::KV0 + ((kt + 1) & 1) * asm_off::STAGE;
            const size_t src = (((size_t)b * H + h) * LK + (kt + 1) * 128 + r) * 64 + halfk;
#pragma unroll
            for (int i = 0; i < 4; i++) {
                uint32_t bo = (uint32_t)(r * 128 + (halfk + i * 8) * 2) ^ swr;
                cp16(sb + bo,         Khi + src + i * 8);
                cp16(sb + 16384 + bo, Klo + src + i * 8);
                cp16(sb + 32768 + bo, Vhi + src + i * 8);
                cp16(sb + 49152 + bo, Vlo + src + i * 8);
            }
            CP_COMMIT();
            CP_WAIT(1);
        } else {
            CP_WAIT(0);
        }
        __syncthreads();

        const uint32_t sKV = sa + asm_off::KV0 + (kt & 1) * asm_off::STAGE;
        const uint32_t qb_ = sa + ((kt < 8) ? 0 : 32768);

        float sacc[16][4];
#pragma unroll
        for (int a = 0; a < 16; a++)
#pragma unroll
            for (int j = 0; j < 4; j++) sacc[a][j] = 0.0f;

#pragma unroll
        for (int kc = 0; kc < 4; ++kc) {
            const int arow = w * 16 + a_r;
            const uint32_t aoff = (uint32_t)(arow * 128) +
                (((uint32_t)(kc * 32 + a_cb)) ^ ((uint32_t)((arow & 7) << 4)));
            uint32_t aqh[4], aql[4];
            ldsm_x4(aqh, qb_ + aoff);
            ldsm_x4(aql, qb_ + 16384 + aoff);
#pragma unroll
            for (int g = 0; g < 8; ++g) {
                const int krow = g * 16 + b_r;
                const uint32_t koff = (uint32_t)(krow * 128) +
                    (((uint32_t)(kc * 32 + b_cb)) ^ ((uint32_t)((krow & 7) << 4)));
                uint32_t kh[4], kl[4];
                ldsm_x4(kh, sKV + koff);
                ldsm_x4(kl, sKV + 16384 + koff);
                mma16816(sacc[2 * g],     aqh, kh);
                mma16816(sacc[2 * g],     aqh, kl);
                mma16816(sacc[2 * g],     aql, kh);
                mma16816(sacc[2 * g + 1], aqh, kh + 2);
                mma16816(sacc[2 * g + 1], aqh, kl + 2);
                mma16816(sacc[2 * g + 1], aql, kh + 2);
            }
        }

        const int kb0 = kt * 128;
        float rmax0 = -1e30f, rmax1 = -1e30f;
#pragma unroll
        for (int na = 0; na < 16; ++na) {
            const float kf0 = kff[kb0 + na * 8 + lc2];
            const float kf1 = kff[kb0 + na * 8 + lc2 + 1];
            float f;
            f = qf0 * kf0; sacc[na][0] = fmaf(sacc[na][0], f, fmaf(1e4f, f, -1e4f));
            f = qf0 * kf1; sacc[na][1] = fmaf(sacc[na][1], f, fmaf(1e4f, f, -1e4f));
            f = qf1 * kf0; sacc[na][2] = fmaf(sacc[na][2], f, fmaf(1e4f, f, -1e4f));
            f = qf1 * kf1; sacc[na][3] = fmaf(sacc[na][3], f, fmaf(1e4f, f, -1e4f));
            rmax0 = fmaxf(rmax0, fmaxf(sacc[na][0], sacc[na][1]));
            rmax1 = fmaxf(rmax1, fmaxf(sacc[na][2], sacc[na][3]));
        }
        rmax0 = fmaxf(rmax0, __shfl_xor_sync(0xffffffffu, rmax0, 1));
        rmax0 = fmaxf(rmax0, __shfl_xor_sync(0xffffffffu, rmax0, 2));
        rmax1 = fmaxf(rmax1, __shfl_xor_sync(0xffffffffu, rmax1, 1));
        rmax1 = fmaxf(rmax1, __shfl_xor_sync(0xffffffffu, rmax1, 2));

        const float mn0 = fmaxf(m0, rmax0), mn1 = fmaxf(m1, rmax1);
        const float sc0 = __expf(m0 - mn0), sc1 = __expf(m1 - mn1);

        float sum0 = 0.0f, sum1 = 0.0f;
#pragma unroll
        for (int na = 0; na < 16; ++na) {
            sacc[na][0] = __expf(sacc[na][0] - mn0);
            sacc[na][1] = __expf(sacc[na][1] - mn0);
            sacc[na][2] = __expf(sacc[na][2] - mn1);
            sacc[na][3] = __expf(sacc[na][3] - mn1);
            sum0 += sacc[na][0] + sacc[na][1];
            sum1 += sacc[na][2] + sacc[na][3];
        }
        sum0 += __shfl_xor_sync(0xffffffffu, sum0, 1);
        sum0 += __shfl_xor_sync(0xffffffffu, sum0, 2);
        sum1 += __shfl_xor_sync(0xffffffffu, sum1, 1);
        sum1 += __shfl_xor_sync(0xffffffffu, sum1, 2);
        l0 = l0 * sc0 + sum0; m0 = mn0;
        l1 = l1 * sc1 + sum1; m1 = mn1;

#pragma unroll
        for (int a = 0; a < 8; a++) {
            oacc[a][0] *= sc0; oacc[a][1] *= sc0;
            oacc[a][2] *= sc1; oacc[a][3] *= sc1;
        }

        const uint32_t sV = sKV + 32768;
#pragma unroll
        for (int kc2 = 0; kc2 < 8; ++kc2) {
            uint32_t ah[4], al[4];
            split2(sacc[2 * kc2][0],     sacc[2 * kc2][1],     ah[0], al[0]);
            split2(sacc[2 * kc2][2],     sacc[2 * kc2][3],     ah[1], al[1]);
            split2(sacc[2 * kc2 + 1][0], sacc[2 * kc2 + 1][1], ah[2], al[2]);
            split2(sacc[2 * kc2 + 1][2], sacc[2 * kc2 + 1][3], ah[3], al[3]);
            const int vrow = kc2 * 16 + (L & 15);
            const uint32_t vsw = (uint32_t)((vrow & 7) << 4);
#pragma unroll
            for (int ng = 0; ng < 4; ++ng) {
                const uint32_t vcolb = (uint32_t)((ng * 16 + ((L >> 4) << 3)) * 2);
                const uint32_t voff = (uint32_t)(vrow * 128) + (vcolb ^ vsw);
                uint32_t bvh[4], bvl[4];
                ldsm_x4_t(bvh, sV + voff);
                ldsm_x4_t(bvl, sV + 16384 + voff);
                mma16816(oacc[2 * ng],     ah, bvh);
                mma16816(oacc[2 * ng],     ah, bvl);
                mma16816(oacc[2 * ng],     al, bvh);
                mma16816(oacc[2 * ng + 1], ah, bvh + 2);
                mma16816(oacc[2 * ng + 1], ah, bvl + 2);
                mma16816(oacc[2 * ng + 1], al, bvh + 2);
            }
        }
    }

    const float scale0 = 0.125f / l0;
    const float scale1 = 0.125f / l1;
    const int qrow0 = q0 + w * 16 + lq;
    float* op0 = obase + ((size_t)(b * Lq + qrow0)) * D + h * 64;
    float* op1 = op0 + (size_t)8 * D;
#pragma unroll
    for (int na = 0; na < 8; ++na) {
        float2 v0 = { oacc[na][0] * scale0, oacc[na][1] * scale0 };
        float2 v1 = { oacc[na][2] * scale1, oacc[na][3] * scale1 };
        *(float2*)(op0 + na * 8 + lc2) = v0;
        *(float2*)(op1 + na * 8 + lc2) = v1;
    }
}

// ---------------------------------------------------------------------------
extern "C" void kernel_launch(void* const* d_in, const int* in_sizes, int n_in,
                              void* d_out, int out_size) {
    using namespace cfg;
    const float* vid_feat = (const float*)d_in[0];
    const void*  vid_mask = d_in[1];
    const float* txt_feat = (const float*)d_in[2];
    const void*  txt_mask = d_in[3];
    const float* W_v2v = (const float*)d_in[4];
    const float* b_v2v = (const float*)d_in[5];
    const float* W_t2v = (const float*)d_in[6];
    const float* b_t2v = (const float*)d_in[7];
    const float* W_v2t = (const float*)d_in[8];
    const float* b_v2t = (const float*)d_in[9];
    const float* W_t2t = (const float*)d_in[10];
    const float* b_t2t = (const float*)d_in[11];
    float* out = (float*)d_out;

    detect_mask_mode<<<1, 32>>>((const unsigned int*)vid_mask);

    // ---- conversions (single launch, grid-stride) ------------------------
    {
        CvtArgs a;
        const float* wv[6] = { W_v2v,          W_t2v,          W_v2v + DD,
                               W_v2t + DD,     W_v2v + 2 * DD, W_v2t + 2 * DD };
        const float* wt[6] = { W_v2t,          W_t2t,          W_t2v + DD,
                               W_t2t + DD,     W_t2v + 2 * DD, W_t2t + 2 * DD };
        a.src[0] = vid_feat; a.dst[0] = 0; a.slot[0] = 0; a.n4[0] = (B * LV * D) / 4;
        a.src[1] = txt_feat; a.dst[1] = 1; a.slot[1] = 0; a.n4[1] = (B * LT * D) / 4;
        for (int s = 0; s < 6; s++) {
            a.src[2 + s] = wv[s]; a.dst[2 + s] = 2; a.slot[2 + s] = s; a.n4[2 + s] = DD / 4;
            a.src[8 + s] = wt[s]; a.dst[8 + s] = 3; a.slot[8 + s] = s; a.n4[8 + s] = DD / 4;
        }
        convert_all<<<dim3(1024, 14), 256>>>(a);
    }

    // ---- projection GEMMs ------------------------------------------------
    const int PROJ_SMEM = 2 * pj::STAGE + 1024;   // 62464
    cudaFuncSetAttribute(proj_mma, cudaFuncAttributeMaxDynamicSharedMemorySize, PROJ_SMEM);

    TCBias bv; bv.p[0] = b_v2v; bv.p[1] = b_t2v; bv.p[2] = b_v2v + D;
               bv.p[3] = b_v2t + D; bv.p[4] = b_v2v + 2 * D; bv.p[5] = b_v2t + 2 * D;
    TCBias bt; bt.p[0] = b_v2t; bt.p[1] = b_t2t; bt.p[2] = b_t2v + D;
               bt.p[3] = b_t2t + D; bt.p[4] = b_t2v + 2 * D; bt.p[5] = b_t2t + 2 * D;

    proj_mma<<<dim3(96, (B * LV) / 128), 256, PROJ_SMEM>>>(1, bv);
    proj_mma<<<dim3(96, (B * LT) / 128), 256, PROJ_SMEM>>>(0, bt);

    // ---- fused attention --------------------------------------------------
    const int ATT_SMEM = 196608 + 512 + 5120 + 1024;   // 203264
    cudaFuncSetAttribute(attn_fused, cudaFuncAttributeMaxDynamicSharedMemorySize, ATT_SMEM);
    attn_fused<<<640, 256, ATT_SMEM>>>(vid_mask, txt_mask, out);
}